// round 1
// baseline (speedup 1.0000x reference)
#include <cuda_runtime.h>
#include <cuda_bf16.h>

// Problem constants
#define N_ROWS   65536      // 64 * 1024 tokens
#define K_CODES  1024
#define D_DIM    64
#define BLOCK_ROWS 128
#define TILE_C   64
#define THREADS  256
#define NUM_BLOCKS (N_ROWS / BLOCK_ROWS)   // 512

// Output layout (floats): [quantized 4194304][loss 1][indices 65536]
#define OUT_Q    0
#define OUT_LOSS (N_ROWS * D_DIM)
#define OUT_IDX  (OUT_LOSS + 1)

__device__ float g_normE[K_CODES];
__device__ float g_partials[NUM_BLOCKS];

// ---------------------------------------------------------------------------
// Kernel 1: codebook squared norms  ||e_k||^2
// ---------------------------------------------------------------------------
__global__ void vq_norm_kernel(const float* __restrict__ E) {
    int k = blockIdx.x * blockDim.x + threadIdx.x;
    if (k < K_CODES) {
        const float4* e = (const float4*)(E + k * D_DIM);
        float s = 0.f;
#pragma unroll
        for (int i = 0; i < D_DIM / 4; ++i) {
            float4 v = e[i];
            s += v.x * v.x + v.y * v.y + v.z * v.z + v.w * v.w;
        }
        g_normE[k] = s;
    }
}

// ---------------------------------------------------------------------------
// Kernel 2: fused distance-GEMM + argmin + gather + partial loss
//   block: 128 rows x all 1024 codes, code tiles of 64, D=64 fully resident
// ---------------------------------------------------------------------------
__global__ __launch_bounds__(THREADS) void vq_main_kernel(
    const float* __restrict__ X,   // [N, D]
    const float* __restrict__ E,   // [K, D]
    float* __restrict__ out)
{
    extern __shared__ float smem[];
    float* As   = smem;                          // [64][128]  (D-major, transposed)
    float* Bs   = As + D_DIM * BLOCK_ROWS;       // [64][64]
    float* redV = Bs + D_DIM * TILE_C;           // [128][16]
    int*   redI = (int*)(redV + BLOCK_ROWS * 16);// [128][16]
    float* sLoss = (float*)(redI + BLOCK_ROWS * 16); // [128]

    const int t = threadIdx.x;
    const int rowBase = blockIdx.x * BLOCK_ROWS;

    // ---- load A tile (128 rows x 64 D), transposed into As[d][r] ----
#pragma unroll
    for (int it = 0; it < 8; ++it) {
        int idx = t + it * THREADS;      // 0..2047
        int r  = idx & 127;
        int d4 = idx >> 7;               // 0..15
        float4 v = *(const float4*)(X + (size_t)(rowBase + r) * D_DIM + d4 * 4);
        As[(d4 * 4 + 0) * BLOCK_ROWS + r] = v.x;
        As[(d4 * 4 + 1) * BLOCK_ROWS + r] = v.y;
        As[(d4 * 4 + 2) * BLOCK_ROWS + r] = v.z;
        As[(d4 * 4 + 3) * BLOCK_ROWS + r] = v.w;
    }

    const int tr = t >> 4;   // 0..15 -> rows tr*8 .. tr*8+7
    const int tc = t & 15;   // 0..15 -> cols tc*4 .. tc*4+3

    float minv[8];
    int   mini[8];
#pragma unroll
    for (int i = 0; i < 8; ++i) { minv[i] = 3.4e38f; mini[i] = 0; }

#pragma unroll 1
    for (int tile = 0; tile < K_CODES / TILE_C; ++tile) {
        __syncthreads();   // As ready (tile 0) / Bs consumed (tile > 0)
        // ---- load B tile (64 codes x 64 D), transposed into Bs[d][c] ----
#pragma unroll
        for (int it = 0; it < 4; ++it) {
            int idx = t + it * THREADS;  // 0..1023
            int c  = idx & 63;
            int d4 = idx >> 6;           // 0..15
            float4 v = *(const float4*)(E + (size_t)(tile * TILE_C + c) * D_DIM + d4 * 4);
            Bs[(d4 * 4 + 0) * TILE_C + c] = v.x;
            Bs[(d4 * 4 + 1) * TILE_C + c] = v.y;
            Bs[(d4 * 4 + 2) * TILE_C + c] = v.z;
            Bs[(d4 * 4 + 3) * TILE_C + c] = v.w;
        }
        __syncthreads();

        float acc[8][4];
#pragma unroll
        for (int i = 0; i < 8; ++i)
#pragma unroll
            for (int j = 0; j < 4; ++j) acc[i][j] = 0.f;

#pragma unroll 16
        for (int d = 0; d < D_DIM; ++d) {
            float4 a0 = *(const float4*)&As[d * BLOCK_ROWS + tr * 8];
            float4 a1 = *(const float4*)&As[d * BLOCK_ROWS + tr * 8 + 4];
            float4 b  = *(const float4*)&Bs[d * TILE_C + tc * 4];
            float a[8] = {a0.x, a0.y, a0.z, a0.w, a1.x, a1.y, a1.z, a1.w};
            float bb[4] = {b.x, b.y, b.z, b.w};
#pragma unroll
            for (int i = 0; i < 8; ++i)
#pragma unroll
                for (int j = 0; j < 4; ++j)
                    acc[i][j] = fmaf(a[i], bb[j], acc[i][j]);
        }

        // ---- tile epilogue: dist = ||e||^2 - 2*dot ; update running argmin ----
#pragma unroll
        for (int j = 0; j < 4; ++j) {
            int code = tile * TILE_C + tc * 4 + j;
            float ne = g_normE[code];
#pragma unroll
            for (int i = 0; i < 8; ++i) {
                float dist = fmaf(-2.f, acc[i][j], ne);
                if (dist < minv[i]) { minv[i] = dist; mini[i] = code; }
            }
        }
    }

    // ---- cross-thread argmin reduction (16 column-threads per row) ----
    __syncthreads();
#pragma unroll
    for (int i = 0; i < 8; ++i) {
        int r = tr * 8 + i;
        redV[r * 16 + tc] = minv[i];
        redI[r * 16 + tc] = mini[i];
    }
    __syncthreads();

    if (t < BLOCK_ROWS) {
        int r = t;
        float bv = redV[r * 16];
        int   bi = redI[r * 16];
#pragma unroll
        for (int j = 1; j < 16; ++j) {
            float v = redV[r * 16 + j];
            int   c = redI[r * 16 + j];
            if (v < bv || (v == bv && c < bi)) { bv = v; bi = c; }
        }

        // gather codebook row, write quantized + index, accumulate loss
        const float4* erow = (const float4*)(E + (size_t)bi * D_DIM);
        float* qout = out + OUT_Q + (size_t)(rowBase + r) * D_DIM;
        float lsum = 0.f;
#pragma unroll
        for (int d4 = 0; d4 < D_DIM / 4; ++d4) {
            float4 q = erow[d4];
            float x0 = As[(d4 * 4 + 0) * BLOCK_ROWS + r];
            float x1 = As[(d4 * 4 + 1) * BLOCK_ROWS + r];
            float x2 = As[(d4 * 4 + 2) * BLOCK_ROWS + r];
            float x3 = As[(d4 * 4 + 3) * BLOCK_ROWS + r];
            float e0 = q.x - x0, e1 = q.y - x1, e2 = q.z - x2, e3 = q.w - x3;
            lsum += e0 * e0 + e1 * e1 + e2 * e2 + e3 * e3;
            *(float4*)(qout + d4 * 4) = q;
        }
        out[OUT_IDX + rowBase + r] = (float)bi;
        sLoss[r] = lsum;
    }
    __syncthreads();

    // deterministic in-block loss reduction (fixed tree)
    if (t < 64) sLoss[t] += sLoss[t + 64];
    __syncthreads();
    if (t < 32) sLoss[t] += sLoss[t + 32];
    __syncthreads();
    if (t == 0) {
        float s = 0.f;
#pragma unroll
        for (int i = 0; i < 32; ++i) s += sLoss[i];
        g_partials[blockIdx.x] = s;
    }
}

// ---------------------------------------------------------------------------
// Kernel 3: deterministic final loss reduction
//   loss = (q_loss + 0.25*e_loss) = 1.25 * mean((q - x)^2)
// ---------------------------------------------------------------------------
__global__ void vq_loss_kernel(float* __restrict__ out) {
    __shared__ float sh[NUM_BLOCKS];
    int t = threadIdx.x;
    sh[t] = g_partials[t];
    __syncthreads();
    for (int s = NUM_BLOCKS / 2; s > 0; s >>= 1) {
        if (t < s) sh[t] += sh[t + s];
        __syncthreads();
    }
    if (t == 0)
        out[OUT_LOSS] = sh[0] * (1.25f / (float)(N_ROWS * D_DIM));
}

// ---------------------------------------------------------------------------
extern "C" void kernel_launch(void* const* d_in, const int* in_sizes, int n_in,
                              void* d_out, int out_size) {
    const float* X = (const float*)d_in[0];   // [64,1024,64] fp32
    const float* E = (const float*)d_in[1];   // [1024,64]   fp32
    float* out = (float*)d_out;

    const int SMEM_BYTES =
        (D_DIM * BLOCK_ROWS + D_DIM * TILE_C + BLOCK_ROWS * 16) * 4  // As,Bs,redV
        + BLOCK_ROWS * 16 * 4                                         // redI
        + BLOCK_ROWS * 4;                                             // sLoss

    cudaFuncSetAttribute(vq_main_kernel,
                         cudaFuncAttributeMaxDynamicSharedMemorySize, SMEM_BYTES);

    vq_norm_kernel<<<(K_CODES + 255) / 256, 256>>>(E);
    vq_main_kernel<<<NUM_BLOCKS, THREADS, SMEM_BYTES>>>(X, E, out);
    vq_loss_kernel<<<1, NUM_BLOCKS>>>(out);
}